// round 9
// baseline (speedup 1.0000x reference)
#include <cuda_runtime.h>
#include <cuda_bf16.h>
#include <math.h>
#include <stdint.h>

#define NN 100000
#define NE 1200000
#define DD 64
#define NG 128
#define CAP 64

// Scratch (device globals: allocation-free rule)
__device__ __align__(16) float d_t[NN * DD];
__device__ __align__(16) float d_bufA[NN * DD];
__device__ __align__(16) float d_bufB[NN * DD];
__device__ __align__(16) float d_g[NG * DD];

// Padded-bucket adjacency
__device__ int d_cnt[NN];
__device__ int d_col[NN * CAP];

// Split bf16 weights, transposed to [n][k] (n<64: Wr col, n>=64: Ws col)
__device__ __align__(16) __nv_bfloat16 d_wbhi[3][128 * 64];
__device__ __align__(16) __nv_bfloat16 d_wblo[3][128 * 64];

typedef unsigned long long ull;

__device__ __forceinline__ void red_add_v4(float* addr, float4 v) {
    asm volatile("red.global.add.v4.f32 [%0], {%1,%2,%3,%4};"
                 :: "l"(addr), "f"(v.x), "f"(v.y), "f"(v.z), "f"(v.w) : "memory");
}
__device__ __forceinline__ void fadd2(ull& d, ull v) {
    asm("add.rn.f32x2 %0, %0, %1;" : "+l"(d) : "l"(v));
}
__device__ __forceinline__ float2 unpack2(ull v) {
    float2 r; asm("mov.b64 {%0,%1}, %2;" : "=f"(r.x), "=f"(r.y) : "l"(v)); return r;
}
__device__ __forceinline__ uint32_t smem_u32(const void* p) {
    uint32_t a;
    asm("{ .reg .u64 t; cvta.to.shared.u64 t, %1; cvt.u32.u64 %0, t; }" : "=r"(a) : "l"(p));
    return a;
}

#define SW128_SWZ(off) ((off) ^ (((off) >> 3) & 0x70))

__device__ __forceinline__ void ldm_x4(uint32_t& r0, uint32_t& r1,
                                       uint32_t& r2, uint32_t& r3, uint32_t addr) {
    asm volatile("ldmatrix.sync.aligned.m8n8.x4.shared.b16 {%0,%1,%2,%3}, [%4];"
                 : "=r"(r0), "=r"(r1), "=r"(r2), "=r"(r3) : "r"(addr));
}

__device__ __forceinline__ void mma16816(float* c, uint32_t a0, uint32_t a1,
                                         uint32_t a2, uint32_t a3,
                                         uint32_t b0, uint32_t b1) {
    asm volatile(
        "mma.sync.aligned.m16n8k16.row.col.f32.bf16.bf16.f32 "
        "{%0,%1,%2,%3}, {%4,%5,%6,%7}, {%8,%9}, {%0,%1,%2,%3};"
        : "+f"(c[0]), "+f"(c[1]), "+f"(c[2]), "+f"(c[3])
        : "r"(a0), "r"(a1), "r"(a2), "r"(a3), "r"(b0), "r"(b1));
}

// SMEM layout: 128 rows x 128B (64 bf16) per tile, SW128-swizzled
#define SM_AHI 0
#define SM_ALO 16384
#define SM_BHI 32768
#define SM_BLO 49152
#define SM_TOTAL 65536

// ---------------- bucket build (4 edges/thread for atomic ILP) ----------------

__global__ void fill_kernel(const int* __restrict__ src,
                            const int* __restrict__ dst, int E) {
    int base = (blockIdx.x * 256 + threadIdx.x) * 4;
#pragma unroll
    for (int u = 0; u < 4; u++) {
        int e = base + u;
        if (e < E) {
            int d = __ldg(&dst[e]);
            int s = __ldg(&src[e]);
            int slot = atomicAdd(&d_cnt[d], 1);
            if (slot < CAP) d_col[d * CAP + slot] = s;
        }
    }
}

// ---------------- weight prep: split + transpose, all 3 layers in one launch --
__global__ void wprep_kernel(const float* __restrict__ Wr1, const float* __restrict__ Ws1,
                             const float* __restrict__ Wr2, const float* __restrict__ Ws2,
                             const float* __restrict__ Wr3, const float* __restrict__ Ws3) {
    int layer = blockIdx.y;
    const float* Wr = (layer == 0) ? Wr1 : (layer == 1) ? Wr2 : Wr3;
    const float* Ws = (layer == 0) ? Ws1 : (layer == 1) ? Ws2 : Ws3;
    int idx = blockIdx.x * 256 + threadIdx.x;
    if (idx >= 128 * 64) return;
    int nn = idx >> 6;
    int k  = idx & 63;
    float w = (nn < 64) ? Wr[k * 64 + nn] : Ws[k * 64 + (nn - 64)];
    __nv_bfloat16 hi = __float2bfloat16(w);
    __nv_bfloat16 lo = __float2bfloat16(w - __bfloat162float(hi));
    d_wbhi[layer][idx] = hi;
    d_wblo[layer][idx] = lo;
}

// ---------------- HMMA dual GEMM (verified R7) ----------------
__global__ __launch_bounds__(256) void gemm_mma_kernel(
    const float* __restrict__ h,
    const __nv_bfloat16* __restrict__ wbhi,
    const __nv_bfloat16* __restrict__ wblo,
    const float* __restrict__ br,
    float* __restrict__ t, float* __restrict__ out, int n)
{
    extern __shared__ char smem[];
    uint32_t sb = smem_u32(smem);
    int tid = threadIdx.x, wid = tid >> 5, lane = tid & 31;
    int row0 = blockIdx.x * 128;

    const float4* h4 = (const float4*)h;
#pragma unroll
    for (int it = 0; it < 8; it++) {
        int lin = tid + it * 256;
        int r  = lin >> 4;
        int q  = lin & 15;
        float4 v = make_float4(0.f, 0.f, 0.f, 0.f);
        if (row0 + r < n) v = h4[(size_t)(row0 + r) * 16 + q];
        __nv_bfloat162 h0 = __floats2bfloat162_rn(v.x, v.y);
        __nv_bfloat162 h1 = __floats2bfloat162_rn(v.z, v.w);
        float2 hf0 = __bfloat1622float2(h0);
        float2 hf1 = __bfloat1622float2(h1);
        __nv_bfloat162 l0 = __floats2bfloat162_rn(v.x - hf0.x, v.y - hf0.y);
        __nv_bfloat162 l1 = __floats2bfloat162_rn(v.z - hf1.x, v.w - hf1.y);
        uint32_t off = SW128_SWZ((uint32_t)(r * 128 + q * 8));
        *(uint2*)(smem + SM_AHI + off) = make_uint2(*(uint32_t*)&h0, *(uint32_t*)&h1);
        *(uint2*)(smem + SM_ALO + off) = make_uint2(*(uint32_t*)&l0, *(uint32_t*)&l1);
    }
    const uint4* bh4 = (const uint4*)wbhi;
    const uint4* bl4 = (const uint4*)wblo;
#pragma unroll
    for (int it = 0; it < 4; it++) {
        int lin = tid + it * 256;
        uint32_t off = SW128_SWZ((uint32_t)(lin * 16));
        *(uint4*)(smem + SM_BHI + off) = bh4[lin];
        *(uint4*)(smem + SM_BLO + off) = bl4[lin];
    }
    __syncthreads();

    float acc[16][4];
#pragma unroll
    for (int i = 0; i < 16; i++)
#pragma unroll
        for (int j = 0; j < 4; j++) acc[i][j] = 0.0f;

    const int mr = wid * 16;
    const int a_row = mr + (lane & 7) + ((lane >> 3) & 1) * 8;
    const int a_kof = ((lane >> 4) & 1) * 8;
    const int b_nof = (lane & 7) + ((lane >> 4) & 1) * 8;
    const int b_kof = ((lane >> 3) & 1) * 8;

    const uint32_t abase[3] = { sb + SM_AHI, sb + SM_AHI, sb + SM_ALO };
    const uint32_t bbase[3] = { sb + SM_BHI, sb + SM_BLO, sb + SM_BHI };

#pragma unroll
    for (int term = 0; term < 3; term++) {
        uint32_t ab = abase[term], bb = bbase[term];
#pragma unroll
        for (int ks = 0; ks < 4; ks++) {
            int kb = ks * 16;
            uint32_t a0, a1, a2, a3;
            {
                uint32_t off = SW128_SWZ((uint32_t)(a_row * 128 + (kb + a_kof) * 2));
                ldm_x4(a0, a1, a2, a3, ab + off);
            }
#pragma unroll
            for (int nb = 0; nb < 8; nb++) {
                uint32_t b0, b1, b2, b3;
                uint32_t off = SW128_SWZ(
                    (uint32_t)((nb * 16 + b_nof) * 128 + (kb + b_kof) * 2));
                ldm_x4(b0, b1, b2, b3, bb + off);
                mma16816(acc[nb * 2],     a0, a1, a2, a3, b0, b1);
                mma16816(acc[nb * 2 + 1], a0, a1, a2, a3, b2, b3);
            }
        }
    }

    int r1 = row0 + mr + (lane >> 2);
    int r2 = r1 + 8;
    int cl = (lane & 3) * 2;
#pragma unroll
    for (int nt = 0; nt < 16; nt++) {
        int c = nt * 8 + cl;
        float2 v1 = make_float2(acc[nt][0], acc[nt][1]);
        float2 v2 = make_float2(acc[nt][2], acc[nt][3]);
        if (c < 64) {
            if (r1 < n) *(float2*)(t + (size_t)r1 * 64 + c) = v1;
            if (r2 < n) *(float2*)(t + (size_t)r2 * 64 + c) = v2;
        } else {
            int cc = c - 64;
            float2 bias = *(const float2*)(br + cc);
            v1.x += bias.x; v1.y += bias.y;
            v2.x += bias.x; v2.y += bias.y;
            if (r1 < n) *(float2*)(out + (size_t)r1 * 64 + cc) = v1;
            if (r2 < n) *(float2*)(out + (size_t)r2 * 64 + cc) = v2;
        }
    }
}

// ---------------- gather: warp per node, 2 edges/step via half-warps ---------
// Lanes 0-15 process edge i, lanes 16-31 edge i+1; each lane loads float4
// (16B x 16 lanes = 256B row). Half-warp partial sums combined via shfl_xor 16.
__global__ __launch_bounds__(256) void gather_kernel(
    const float* __restrict__ t, const float* __restrict__ base,
    float* __restrict__ out, const int* __restrict__ batch, int n, int mode)
{
    int warp = threadIdx.x >> 5;
    int lane = threadIdx.x & 31;
    int half = lane >> 4;       // 0 or 1
    int hl   = lane & 15;       // float4 index within row
    int node = blockIdx.x * 8 + warp;
    if (node >= n) return;

    int deg = d_cnt[node];
    if (deg > CAP) deg = CAP;
    const int* col = d_col + node * CAP;
    const float4* t4 = (const float4*)t;

    ull accx = 0, accy = 0;
    if (half == 0) {
        const ull* b2 = (const ull*)base;
        accx = b2[(size_t)node * 32 + hl * 2];
        accy = b2[(size_t)node * 32 + hl * 2 + 1];
    }

    for (int j = 0; j < deg; j += 32) {
        int rem = deg - j;
        int cnt = rem < 32 ? rem : 32;
        int id = 0;
        if (lane < cnt) id = col[j + lane];
        int i = 0;
        for (; i + 8 <= cnt; i += 8) {
            int e0 = __shfl_sync(0xffffffffu, id, i     + half);
            int e1 = __shfl_sync(0xffffffffu, id, i + 2 + half);
            int e2 = __shfl_sync(0xffffffffu, id, i + 4 + half);
            int e3 = __shfl_sync(0xffffffffu, id, i + 6 + half);
            float4 v0 = t4[(size_t)e0 * 16 + hl];
            float4 v1 = t4[(size_t)e1 * 16 + hl];
            float4 v2 = t4[(size_t)e2 * 16 + hl];
            float4 v3 = t4[(size_t)e3 * 16 + hl];
            ull* p0 = (ull*)&v0; fadd2(accx, p0[0]); fadd2(accy, p0[1]);
            ull* p1 = (ull*)&v1; fadd2(accx, p1[0]); fadd2(accy, p1[1]);
            ull* p2 = (ull*)&v2; fadd2(accx, p2[0]); fadd2(accy, p2[1]);
            ull* p3 = (ull*)&v3; fadd2(accx, p3[0]); fadd2(accy, p3[1]);
        }
        for (; i + 2 <= cnt; i += 2) {
            int e = __shfl_sync(0xffffffffu, id, i + half);
            float4 v = t4[(size_t)e * 16 + hl];
            ull* p = (ull*)&v; fadd2(accx, p[0]); fadd2(accy, p[1]);
        }
        if (i < cnt) {
            int e = __shfl_sync(0xffffffffu, id, i);
            if (half == 0) {
                float4 v = t4[(size_t)e * 16 + hl];
                ull* p = (ull*)&v; fadd2(accx, p[0]); fadd2(accy, p[1]);
            }
        }
    }

    // combine half-warps
    ull ox = __shfl_xor_sync(0xffffffffu, accx, 16);
    ull oy = __shfl_xor_sync(0xffffffffu, accy, 16);
    fadd2(accx, ox);
    fadd2(accy, oy);

    if (half == 0) {
        float2 vx = unpack2(accx);
        float2 vy = unpack2(accy);
        float4 v = make_float4(fmaxf(vx.x, 0.f), fmaxf(vx.y, 0.f),
                               fmaxf(vy.x, 0.f), fmaxf(vy.y, 0.f));
        if (mode == 0) {
            ((float4*)out)[(size_t)node * 16 + hl] = v;
        } else {
            int b = __ldg(&batch[node]);
            red_add_v4(&d_g[b * 64 + hl * 4], v);
        }
    }
}

// ---------------- MLP head (unchanged) ----------------
__global__ __launch_bounds__(128) void head_kernel(
    const float* __restrict__ W1, const float* __restrict__ b1,
    const float* __restrict__ W2, const float* __restrict__ b2,
    float* __restrict__ out)
{
    __shared__ float sW1[64 * 64];
    __shared__ float sb1[64];
    __shared__ float sW2[64 * 3];
    __shared__ float sb2[3];
    for (int i = threadIdx.x; i < 64 * 64; i += 128) sW1[i] = W1[i];
    if (threadIdx.x < 64) sb1[threadIdx.x] = b1[threadIdx.x];
    for (int i = threadIdx.x; i < 64 * 3; i += 128) sW2[i] = W2[i];
    if (threadIdx.x < 3) sb2[threadIdx.x] = b2[threadIdx.x];
    __syncthreads();

    int warp = threadIdx.x >> 5;
    int lane = threadIdx.x & 31;
    int gi = blockIdx.x * 4 + warp;
    if (gi >= NG) return;

    float g0 = d_g[gi * 64 + lane];
    float g1 = d_g[gi * 64 + 32 + lane];
    float h0 = sb1[lane];
    float h1 = sb1[lane + 32];
#pragma unroll
    for (int k = 0; k < 32; k++) {
        float gk = __shfl_sync(0xffffffffu, g0, k);
        h0 = fmaf(gk, sW1[k * 64 + lane], h0);
        h1 = fmaf(gk, sW1[k * 64 + 32 + lane], h1);
    }
#pragma unroll
    for (int k = 0; k < 32; k++) {
        float gk = __shfl_sync(0xffffffffu, g1, k);
        h0 = fmaf(gk, sW1[(k + 32) * 64 + lane], h0);
        h1 = fmaf(gk, sW1[(k + 32) * 64 + 32 + lane], h1);
    }
    h0 = fmaxf(h0, 0.f);
    h1 = fmaxf(h1, 0.f);

    float l0 = h0 * sW2[lane * 3 + 0] + h1 * sW2[(lane + 32) * 3 + 0];
    float l1 = h0 * sW2[lane * 3 + 1] + h1 * sW2[(lane + 32) * 3 + 1];
    float l2 = h0 * sW2[lane * 3 + 2] + h1 * sW2[(lane + 32) * 3 + 2];
#pragma unroll
    for (int o = 16; o > 0; o >>= 1) {
        l0 += __shfl_xor_sync(0xffffffffu, l0, o);
        l1 += __shfl_xor_sync(0xffffffffu, l1, o);
        l2 += __shfl_xor_sync(0xffffffffu, l2, o);
    }
    if (lane == 0) {
        l0 += sb2[0]; l1 += sb2[1]; l2 += sb2[2];
        float m = fmaxf(l0, fmaxf(l1, l2));
        float lse = m + logf(expf(l0 - m) + expf(l1 - m) + expf(l2 - m));
        out[gi * 3 + 0] = l0 - lse;
        out[gi * 3 + 1] = l1 - lse;
        out[gi * 3 + 2] = l2 - lse;
    }
}

extern "C" void kernel_launch(void* const* d_in, const int* in_sizes, int n_in,
                              void* d_out, int out_size)
{
    const float* x     = (const float*)d_in[0];
    const int*   ei    = (const int*)  d_in[1];
    const int*   batch = (const int*)  d_in[2];
    const float* Wr1 = (const float*)d_in[3];
    const float* br1 = (const float*)d_in[4];
    const float* Ws1 = (const float*)d_in[5];
    const float* Wr2 = (const float*)d_in[6];
    const float* br2 = (const float*)d_in[7];
    const float* Ws2 = (const float*)d_in[8];
    const float* Wr3 = (const float*)d_in[9];
    const float* br3 = (const float*)d_in[10];
    const float* Ws3 = (const float*)d_in[11];
    const float* Wf1 = (const float*)d_in[12];
    const float* bf1 = (const float*)d_in[13];
    const float* Wf2 = (const float*)d_in[14];
    const float* bf2 = (const float*)d_in[15];

    int n = in_sizes[0] / DD;     // 100000
    int E = in_sizes[1] / 2;      // 1200000
    const int* src = ei;
    const int* dst = ei + E;

    float *t, *bufA, *bufB, *gptr;
    int *cntptr;
    __nv_bfloat16 *wbhi, *wblo;
    cudaGetSymbolAddress((void**)&t,      d_t);
    cudaGetSymbolAddress((void**)&bufA,   d_bufA);
    cudaGetSymbolAddress((void**)&bufB,   d_bufB);
    cudaGetSymbolAddress((void**)&gptr,   d_g);
    cudaGetSymbolAddress((void**)&cntptr, d_cnt);
    cudaGetSymbolAddress((void**)&wbhi,   d_wbhi);
    cudaGetSymbolAddress((void**)&wblo,   d_wblo);

    cudaFuncSetAttribute(gemm_mma_kernel,
                         cudaFuncAttributeMaxDynamicSharedMemorySize, SM_TOTAL);

    int gemm_grid   = (n + 127) / 128;
    int gather_grid = (n + 7) / 8;
    int fill_grid   = (E / 4 + 255) / 256;

    // --- bucket adjacency + weight prep ---
    cudaMemsetAsync(cntptr, 0, NN * sizeof(int));
    cudaMemsetAsync(gptr,   0, NG * DD * sizeof(float));
    fill_kernel<<<fill_grid, 256>>>(src, dst, E);
    dim3 wp_grid((128 * 64 + 255) / 256, 3);
    wprep_kernel<<<wp_grid, 256>>>(Wr1, Ws1, Wr2, Ws2, Wr3, Ws3);

    // --- 3 GraphConv layers (relu folded into gather write) ---
    gemm_mma_kernel<<<gemm_grid, 256, SM_TOTAL>>>(x, wbhi + 0 * 8192, wblo + 0 * 8192, br1, t, bufA, n);
    gather_kernel<<<gather_grid, 256>>>(t, bufA, bufA, batch, n, 0);
    gemm_mma_kernel<<<gemm_grid, 256, SM_TOTAL>>>(bufA, wbhi + 1 * 8192, wblo + 1 * 8192, br2, t, bufB, n);
    gather_kernel<<<gather_grid, 256>>>(t, bufB, bufB, batch, n, 0);
    gemm_mma_kernel<<<gemm_grid, 256, SM_TOTAL>>>(bufB, wbhi + 2 * 8192, wblo + 2 * 8192, br3, t, bufA, n);
    gather_kernel<<<gather_grid, 256>>>(t, bufA, nullptr, batch, n, 1);

    head_kernel<<<32, 128>>>(Wf1, bf1, Wf2, bf2, (float*)d_out);
}

// round 10
// speedup vs baseline: 1.1593x; 1.1593x over previous
#include <cuda_runtime.h>
#include <cuda_bf16.h>
#include <math.h>
#include <stdint.h>

#define NN 100000
#define NE 1200000
#define DD 64
#define NG 128
#define CAP 64

// Scratch (device globals: allocation-free rule)
__device__ __align__(16) float d_t[NN * DD];
__device__ __align__(16) float d_bufA[NN * DD];
__device__ __align__(16) float d_bufB[NN * DD];
__device__ __align__(16) float d_g[NG * DD];

// Padded-bucket adjacency
__device__ int d_cnt[NN];
__device__ int d_col[NN * CAP];

// Split bf16 weights, transposed to [n][k] (n<64: Wr col, n>=64: Ws col)
__device__ __align__(16) __nv_bfloat16 d_wbhi[3][128 * 64];
__device__ __align__(16) __nv_bfloat16 d_wblo[3][128 * 64];

typedef unsigned long long ull;

__device__ __forceinline__ void red_add_v2(float* addr, float a, float b) {
    asm volatile("red.global.add.v2.f32 [%0], {%1,%2};"
                 :: "l"(addr), "f"(a), "f"(b) : "memory");
}
__device__ __forceinline__ void fadd2(ull& d, ull v) {
    asm("add.rn.f32x2 %0, %0, %1;" : "+l"(d) : "l"(v));
}
__device__ __forceinline__ float2 unpack2(ull v) {
    float2 r; asm("mov.b64 {%0,%1}, %2;" : "=f"(r.x), "=f"(r.y) : "l"(v)); return r;
}
__device__ __forceinline__ uint32_t smem_u32(const void* p) {
    uint32_t a;
    asm("{ .reg .u64 t; cvta.to.shared.u64 t, %1; cvt.u32.u64 %0, t; }" : "=r"(a) : "l"(p));
    return a;
}

#define SW128_SWZ(off) ((off) ^ (((off) >> 3) & 0x70))

__device__ __forceinline__ void ldm_x4(uint32_t& r0, uint32_t& r1,
                                       uint32_t& r2, uint32_t& r3, uint32_t addr) {
    asm volatile("ldmatrix.sync.aligned.m8n8.x4.shared.b16 {%0,%1,%2,%3}, [%4];"
                 : "=r"(r0), "=r"(r1), "=r"(r2), "=r"(r3) : "r"(addr));
}

__device__ __forceinline__ void mma16816(float* c, uint32_t a0, uint32_t a1,
                                         uint32_t a2, uint32_t a3,
                                         uint32_t b0, uint32_t b1) {
    asm volatile(
        "mma.sync.aligned.m16n8k16.row.col.f32.bf16.bf16.f32 "
        "{%0,%1,%2,%3}, {%4,%5,%6,%7}, {%8,%9}, {%0,%1,%2,%3};"
        : "+f"(c[0]), "+f"(c[1]), "+f"(c[2]), "+f"(c[3])
        : "r"(a0), "r"(a1), "r"(a2), "r"(a3), "r"(b0), "r"(b1));
}

// SMEM layout: 128 rows x 128B (64 bf16) per tile, SW128-swizzled
#define SM_AHI 0
#define SM_ALO 16384
#define SM_BHI 32768
#define SM_BLO 49152
#define SM_TOTAL 65536

// ---------------- bucket build (4 edges/thread for atomic ILP) ----------------

__global__ void fill_kernel(const int* __restrict__ src,
                            const int* __restrict__ dst, int E) {
    int base = (blockIdx.x * 256 + threadIdx.x) * 4;
#pragma unroll
    for (int u = 0; u < 4; u++) {
        int e = base + u;
        if (e < E) {
            int d = __ldg(&dst[e]);
            int s = __ldg(&src[e]);
            int slot = atomicAdd(&d_cnt[d], 1);
            if (slot < CAP) d_col[d * CAP + slot] = s;
        }
    }
}

// ---------------- weight prep: split + transpose, all 3 layers in one launch --
__global__ void wprep_kernel(const float* __restrict__ Wr1, const float* __restrict__ Ws1,
                             const float* __restrict__ Wr2, const float* __restrict__ Ws2,
                             const float* __restrict__ Wr3, const float* __restrict__ Ws3) {
    int layer = blockIdx.y;
    const float* Wr = (layer == 0) ? Wr1 : (layer == 1) ? Wr2 : Wr3;
    const float* Ws = (layer == 0) ? Ws1 : (layer == 1) ? Ws2 : Ws3;
    int idx = blockIdx.x * 256 + threadIdx.x;
    if (idx >= 128 * 64) return;
    int nn = idx >> 6;
    int k  = idx & 63;
    float w = (nn < 64) ? Wr[k * 64 + nn] : Ws[k * 64 + (nn - 64)];
    __nv_bfloat16 hi = __float2bfloat16(w);
    __nv_bfloat16 lo = __float2bfloat16(w - __bfloat162float(hi));
    d_wbhi[layer][idx] = hi;
    d_wblo[layer][idx] = lo;
}

// ---------------- HMMA dual GEMM (verified R7) ----------------
__global__ __launch_bounds__(256) void gemm_mma_kernel(
    const float* __restrict__ h,
    const __nv_bfloat16* __restrict__ wbhi,
    const __nv_bfloat16* __restrict__ wblo,
    const float* __restrict__ br,
    float* __restrict__ t, float* __restrict__ out, int n)
{
    extern __shared__ char smem[];
    uint32_t sb = smem_u32(smem);
    int tid = threadIdx.x, wid = tid >> 5, lane = tid & 31;
    int row0 = blockIdx.x * 128;

    const float4* h4 = (const float4*)h;
#pragma unroll
    for (int it = 0; it < 8; it++) {
        int lin = tid + it * 256;
        int r  = lin >> 4;
        int q  = lin & 15;
        float4 v = make_float4(0.f, 0.f, 0.f, 0.f);
        if (row0 + r < n) v = h4[(size_t)(row0 + r) * 16 + q];
        __nv_bfloat162 h0 = __floats2bfloat162_rn(v.x, v.y);
        __nv_bfloat162 h1 = __floats2bfloat162_rn(v.z, v.w);
        float2 hf0 = __bfloat1622float2(h0);
        float2 hf1 = __bfloat1622float2(h1);
        __nv_bfloat162 l0 = __floats2bfloat162_rn(v.x - hf0.x, v.y - hf0.y);
        __nv_bfloat162 l1 = __floats2bfloat162_rn(v.z - hf1.x, v.w - hf1.y);
        uint32_t off = SW128_SWZ((uint32_t)(r * 128 + q * 8));
        *(uint2*)(smem + SM_AHI + off) = make_uint2(*(uint32_t*)&h0, *(uint32_t*)&h1);
        *(uint2*)(smem + SM_ALO + off) = make_uint2(*(uint32_t*)&l0, *(uint32_t*)&l1);
    }
    const uint4* bh4 = (const uint4*)wbhi;
    const uint4* bl4 = (const uint4*)wblo;
#pragma unroll
    for (int it = 0; it < 4; it++) {
        int lin = tid + it * 256;
        uint32_t off = SW128_SWZ((uint32_t)(lin * 16));
        *(uint4*)(smem + SM_BHI + off) = bh4[lin];
        *(uint4*)(smem + SM_BLO + off) = bl4[lin];
    }
    __syncthreads();

    float acc[16][4];
#pragma unroll
    for (int i = 0; i < 16; i++)
#pragma unroll
        for (int j = 0; j < 4; j++) acc[i][j] = 0.0f;

    const int mr = wid * 16;
    const int a_row = mr + (lane & 7) + ((lane >> 3) & 1) * 8;
    const int a_kof = ((lane >> 4) & 1) * 8;
    const int b_nof = (lane & 7) + ((lane >> 4) & 1) * 8;
    const int b_kof = ((lane >> 3) & 1) * 8;

    const uint32_t abase[3] = { sb + SM_AHI, sb + SM_AHI, sb + SM_ALO };
    const uint32_t bbase[3] = { sb + SM_BHI, sb + SM_BLO, sb + SM_BHI };

#pragma unroll
    for (int term = 0; term < 3; term++) {
        uint32_t ab = abase[term], bb = bbase[term];
#pragma unroll
        for (int ks = 0; ks < 4; ks++) {
            int kb = ks * 16;
            uint32_t a0, a1, a2, a3;
            {
                uint32_t off = SW128_SWZ((uint32_t)(a_row * 128 + (kb + a_kof) * 2));
                ldm_x4(a0, a1, a2, a3, ab + off);
            }
#pragma unroll
            for (int nb = 0; nb < 8; nb++) {
                uint32_t b0, b1, b2, b3;
                uint32_t off = SW128_SWZ(
                    (uint32_t)((nb * 16 + b_nof) * 128 + (kb + b_kof) * 2));
                ldm_x4(b0, b1, b2, b3, bb + off);
                mma16816(acc[nb * 2],     a0, a1, a2, a3, b0, b1);
                mma16816(acc[nb * 2 + 1], a0, a1, a2, a3, b2, b3);
            }
        }
    }

    int r1 = row0 + mr + (lane >> 2);
    int r2 = r1 + 8;
    int cl = (lane & 3) * 2;
#pragma unroll
    for (int nt = 0; nt < 16; nt++) {
        int c = nt * 8 + cl;
        float2 v1 = make_float2(acc[nt][0], acc[nt][1]);
        float2 v2 = make_float2(acc[nt][2], acc[nt][3]);
        if (c < 64) {
            if (r1 < n) *(float2*)(t + (size_t)r1 * 64 + c) = v1;
            if (r2 < n) *(float2*)(t + (size_t)r2 * 64 + c) = v2;
        } else {
            int cc = c - 64;
            float2 bias = *(const float2*)(br + cc);
            v1.x += bias.x; v1.y += bias.y;
            v2.x += bias.x; v2.y += bias.y;
            if (r1 < n) *(float2*)(out + (size_t)r1 * 64 + cc) = v1;
            if (r2 < n) *(float2*)(out + (size_t)r2 * 64 + cc) = v2;
        }
    }
}

// ---------------- gather: exact R7 version (measured ~39us/pass) ----------------
__global__ __launch_bounds__(256) void gather_kernel(
    const float* __restrict__ t, const float* __restrict__ base,
    float* __restrict__ out, const int* __restrict__ batch, int n, int mode)
{
    int warp = threadIdx.x >> 5;
    int lane = threadIdx.x & 31;
    int node = blockIdx.x * 8 + warp;
    if (node >= n) return;

    int deg = d_cnt[node];
    if (deg > CAP) deg = CAP;
    const int* col = d_col + node * CAP;

    const ull* t2 = (const ull*)t;
    ull acc = ((const ull*)base)[node * 32 + lane];

    for (int j = 0; j < deg; j += 32) {
        int rem = deg - j;
        int cnt = rem < 32 ? rem : 32;
        int id = 0;
        if (lane < cnt) id = col[j + lane];
        int i = 0;
        for (; i + 4 <= cnt; i += 4) {
            int e0 = __shfl_sync(0xffffffffu, id, i);
            int e1 = __shfl_sync(0xffffffffu, id, i + 1);
            int e2 = __shfl_sync(0xffffffffu, id, i + 2);
            int e3 = __shfl_sync(0xffffffffu, id, i + 3);
            ull v0 = t2[e0 * 32 + lane];
            ull v1 = t2[e1 * 32 + lane];
            ull v2 = t2[e2 * 32 + lane];
            ull v3 = t2[e3 * 32 + lane];
            fadd2(acc, v0);
            fadd2(acc, v1);
            fadd2(acc, v2);
            fadd2(acc, v3);
        }
        for (; i < cnt; i++) {
            int s = __shfl_sync(0xffffffffu, id, i);
            fadd2(acc, t2[s * 32 + lane]);
        }
    }

    float2 v = unpack2(acc);
    v.x = fmaxf(v.x, 0.0f);
    v.y = fmaxf(v.y, 0.0f);
    if (mode == 0) {
        ((float2*)out)[node * 32 + lane] = v;
    } else {
        int b = __ldg(&batch[node]);
        red_add_v2(&d_g[b * 64 + lane * 2], v.x, v.y);
    }
}

// ---------------- MLP head (unchanged) ----------------
__global__ __launch_bounds__(128) void head_kernel(
    const float* __restrict__ W1, const float* __restrict__ b1,
    const float* __restrict__ W2, const float* __restrict__ b2,
    float* __restrict__ out)
{
    __shared__ float sW1[64 * 64];
    __shared__ float sb1[64];
    __shared__ float sW2[64 * 3];
    __shared__ float sb2[3];
    for (int i = threadIdx.x; i < 64 * 64; i += 128) sW1[i] = W1[i];
    if (threadIdx.x < 64) sb1[threadIdx.x] = b1[threadIdx.x];
    for (int i = threadIdx.x; i < 64 * 3; i += 128) sW2[i] = W2[i];
    if (threadIdx.x < 3) sb2[threadIdx.x] = b2[threadIdx.x];
    __syncthreads();

    int warp = threadIdx.x >> 5;
    int lane = threadIdx.x & 31;
    int gi = blockIdx.x * 4 + warp;
    if (gi >= NG) return;

    float g0 = d_g[gi * 64 + lane];
    float g1 = d_g[gi * 64 + 32 + lane];
    float h0 = sb1[lane];
    float h1 = sb1[lane + 32];
#pragma unroll
    for (int k = 0; k < 32; k++) {
        float gk = __shfl_sync(0xffffffffu, g0, k);
        h0 = fmaf(gk, sW1[k * 64 + lane], h0);
        h1 = fmaf(gk, sW1[k * 64 + 32 + lane], h1);
    }
#pragma unroll
    for (int k = 0; k < 32; k++) {
        float gk = __shfl_sync(0xffffffffu, g1, k);
        h0 = fmaf(gk, sW1[(k + 32) * 64 + lane], h0);
        h1 = fmaf(gk, sW1[(k + 32) * 64 + 32 + lane], h1);
    }
    h0 = fmaxf(h0, 0.f);
    h1 = fmaxf(h1, 0.f);

    float l0 = h0 * sW2[lane * 3 + 0] + h1 * sW2[(lane + 32) * 3 + 0];
    float l1 = h0 * sW2[lane * 3 + 1] + h1 * sW2[(lane + 32) * 3 + 1];
    float l2 = h0 * sW2[lane * 3 + 2] + h1 * sW2[(lane + 32) * 3 + 2];
#pragma unroll
    for (int o = 16; o > 0; o >>= 1) {
        l0 += __shfl_xor_sync(0xffffffffu, l0, o);
        l1 += __shfl_xor_sync(0xffffffffu, l1, o);
        l2 += __shfl_xor_sync(0xffffffffu, l2, o);
    }
    if (lane == 0) {
        l0 += sb2[0]; l1 += sb2[1]; l2 += sb2[2];
        float m = fmaxf(l0, fmaxf(l1, l2));
        float lse = m + logf(expf(l0 - m) + expf(l1 - m) + expf(l2 - m));
        out[gi * 3 + 0] = l0 - lse;
        out[gi * 3 + 1] = l1 - lse;
        out[gi * 3 + 2] = l2 - lse;
    }
}

extern "C" void kernel_launch(void* const* d_in, const int* in_sizes, int n_in,
                              void* d_out, int out_size)
{
    const float* x     = (const float*)d_in[0];
    const int*   ei    = (const int*)  d_in[1];
    const int*   batch = (const int*)  d_in[2];
    const float* Wr1 = (const float*)d_in[3];
    const float* br1 = (const float*)d_in[4];
    const float* Ws1 = (const float*)d_in[5];
    const float* Wr2 = (const float*)d_in[6];
    const float* br2 = (const float*)d_in[7];
    const float* Ws2 = (const float*)d_in[8];
    const float* Wr3 = (const float*)d_in[9];
    const float* br3 = (const float*)d_in[10];
    const float* Ws3 = (const float*)d_in[11];
    const float* Wf1 = (const float*)d_in[12];
    const float* bf1 = (const float*)d_in[13];
    const float* Wf2 = (const float*)d_in[14];
    const float* bf2 = (const float*)d_in[15];

    int n = in_sizes[0] / DD;     // 100000
    int E = in_sizes[1] / 2;      // 1200000
    const int* src = ei;
    const int* dst = ei + E;

    float *t, *bufA, *bufB, *gptr;
    int *cntptr;
    __nv_bfloat16 *wbhi, *wblo;
    cudaGetSymbolAddress((void**)&t,      d_t);
    cudaGetSymbolAddress((void**)&bufA,   d_bufA);
    cudaGetSymbolAddress((void**)&bufB,   d_bufB);
    cudaGetSymbolAddress((void**)&gptr,   d_g);
    cudaGetSymbolAddress((void**)&cntptr, d_cnt);
    cudaGetSymbolAddress((void**)&wbhi,   d_wbhi);
    cudaGetSymbolAddress((void**)&wblo,   d_wblo);

    cudaFuncSetAttribute(gemm_mma_kernel,
                         cudaFuncAttributeMaxDynamicSharedMemorySize, SM_TOTAL);

    int gemm_grid   = (n + 127) / 128;
    int gather_grid = (n + 7) / 8;
    int fill_grid   = (E / 4 + 255) / 256;

    // --- bucket adjacency + weight prep ---
    cudaMemsetAsync(cntptr, 0, NN * sizeof(int));
    cudaMemsetAsync(gptr,   0, NG * DD * sizeof(float));
    fill_kernel<<<fill_grid, 256>>>(src, dst, E);
    dim3 wp_grid((128 * 64 + 255) / 256, 3);
    wprep_kernel<<<wp_grid, 256>>>(Wr1, Ws1, Wr2, Ws2, Wr3, Ws3);

    // --- 3 GraphConv layers (relu folded into gather write) ---
    gemm_mma_kernel<<<gemm_grid, 256, SM_TOTAL>>>(x, wbhi + 0 * 8192, wblo + 0 * 8192, br1, t, bufA, n);
    gather_kernel<<<gather_grid, 256>>>(t, bufA, bufA, batch, n, 0);
    gemm_mma_kernel<<<gemm_grid, 256, SM_TOTAL>>>(bufA, wbhi + 1 * 8192, wblo + 1 * 8192, br2, t, bufB, n);
    gather_kernel<<<gather_grid, 256>>>(t, bufB, bufB, batch, n, 0);
    gemm_mma_kernel<<<gemm_grid, 256, SM_TOTAL>>>(bufB, wbhi + 2 * 8192, wblo + 2 * 8192, br3, t, bufA, n);
    gather_kernel<<<gather_grid, 256>>>(t, bufA, nullptr, batch, n, 1);

    head_kernel<<<32, 128>>>(Wf1, bf1, Wf2, bf2, (float*)d_out);
}